// round 6
// baseline (speedup 1.0000x reference)
#include <cuda_runtime.h>
#include <cstdint>

#define MAPSZ 38809      // 197*197
#define NP    196        // 14*14 patches
#define HW    784        // 28*28
#define THRPT 160

// scratch[(i*32 + b)*196 + p] = sum over j (12 heads) of att[i,b,j,0,1+p]
__device__ float g_scratch[12 * 32 * NP];

// ---------------- Kernel 1: wide phase-A reduction (384 blocks) ----------------
__global__ __launch_bounds__(224)
void phaseA_kernel(const float* __restrict__ att)
{
    const int i = blockIdx.x;      // layer 0..11
    const int b = blockIdx.y;      // batch 0..31
    const int p = threadIdx.x;     // patch 0..195
    if (p >= NP) return;

    const float* base = att + (size_t)(i * 384 + b * 12) * MAPSZ + 1 + p;
    float s0 = 0.f, s1 = 0.f, s2 = 0.f, s3 = 0.f;
    #pragma unroll
    for (int j = 0; j < 12; j += 4) {
        s0 += __ldg(base + (size_t)(j + 0) * MAPSZ);
        s1 += __ldg(base + (size_t)(j + 1) * MAPSZ);
        s2 += __ldg(base + (size_t)(j + 2) * MAPSZ);
        s3 += __ldg(base + (size_t)(j + 3) * MAPSZ);
    }
    g_scratch[(i * 32 + b) * NP + p] = (s0 + s1) + (s2 + s3);
}

// ---------------- Kernel 2: threshold, CCL, compaction (32 blocks) ----------------
__global__ __launch_bounds__(1024, 1)
void maskgen_kernel(float* __restrict__ out)
{
    __shared__ float sh_a14[NP];       // 14x14 attention means
    __shared__ float sh_red[256];      // threshold reduction
    __shared__ int   sh_lab[HW];       // CCL labels (HW = background)
    __shared__ int   sh_cnt[HW];       // per-label counts
    __shared__ int   sh_wsum[32], sh_wpre[32];
    __shared__ int   sh_changed, sh_key, sh_total;
    __shared__ float sh_thr;

    const int b   = blockIdx.x;
    const int tid = threadIdx.x;

    // ---------- gather partial sums (L2-resident scratch) ----------
    if (tid < NP) {
        float s0 = 0.f, s1 = 0.f, s2 = 0.f, s3 = 0.f;
        #pragma unroll
        for (int i = 0; i < 12; i += 4) {
            s0 += g_scratch[((i + 0) * 32 + b) * NP + tid];
            s1 += g_scratch[((i + 1) * 32 + b) * NP + tid];
            s2 += g_scratch[((i + 2) * 32 + b) * NP + tid];
            s3 += g_scratch[((i + 3) * 32 + b) * NP + tid];
        }
        sh_a14[tid] = ((s0 + s1) + (s2 + s3)) / 144.0f;
    }
    __syncthreads();

    // ---------- threshold = mean of a14 (== mean of 28x28 upsample) ----------
    if (tid < 256) sh_red[tid] = (tid < NP) ? sh_a14[tid] : 0.f;
    __syncthreads();
    for (int s = 128; s > 0; s >>= 1) {
        if (tid < s) sh_red[tid] += sh_red[tid + s];
        __syncthreads();
    }
    if (tid == 0) {
        sh_thr = sh_red[0] / 196.0f;
        sh_key = 0;
        sh_changed = 0;
    }
    __syncthreads();
    const float thr = sh_thr;

    // ---------- mask (nearest 2x upsample) + label init ----------
    if (tid < HW) {
        int y = tid / 28, x = tid - y * 28;
        bool m = sh_a14[(y >> 1) * 14 + (x >> 1)] > thr;
        sh_lab[tid] = m ? tid : HW;
        sh_cnt[tid] = 0;
    }
    __syncthreads();

    // ---------- CCL: neighbor-min + pointer jumping to fixed point ----------
    // Fixed point == per-component min flat index == reference's 784 Jacobi iters.
    // Monotone-min: in-place races are benign (any read is a valid upper bound).
    for (int it = 0; it < HW; ++it) {
        bool ch = false;
        if (tid < HW && sh_lab[tid] < HW) {
            int c = tid;
            int v = sh_lab[c];
            int y = c / 28, x = c - y * 28;
            if (y > 0)  v = min(v, sh_lab[c - 28]);
            if (y < 27) v = min(v, sh_lab[c + 28]);
            if (x > 0)  v = min(v, sh_lab[c - 1]);
            if (x < 27) v = min(v, sh_lab[c + 1]);
            v = sh_lab[v];   // pointer jump (label values are fg seed indices)
            v = sh_lab[v];
            if (v < sh_lab[c]) { sh_lab[c] = v; ch = true; }
        }
        if (ch) sh_changed = 1;
        __syncthreads();
        int done = (sh_changed == 0);
        __syncthreads();
        if (done) break;
        if (tid == 0) sh_changed = 0;
        __syncthreads();
    }

    // ---------- component areas, argmax (ties -> smallest label) ----------
    if (tid < HW && sh_lab[tid] < HW) atomicAdd(&sh_cnt[sh_lab[tid]], 1);
    __syncthreads();
    if (tid < HW && sh_cnt[tid] > 0) {
        int key = (sh_cnt[tid] << 10) | (1023 - tid);   // count<=784, label<784
        atomicMax(&sh_key, key);
    }
    __syncthreads();
    const int maxArea = sh_key >> 10;
    const int maxLab  = 1023 - (sh_key & 1023);
    const bool keep   = (maxArea >= THRPT);

    int f = 0;
    if (tid < HW) f = keep ? (sh_lab[tid] == maxLab) : (sh_lab[tid] < HW);

    // ---------- stable "fg indices first, then bg" compaction ----------
    unsigned bal = __ballot_sync(0xFFFFFFFFu, f);
    const int lane = tid & 31, w = tid >> 5;
    const int lanepre = __popc(bal & ((1u << lane) - 1));
    if (lane == 0) sh_wsum[w] = __popc(bal);
    __syncthreads();
    if (w == 0) {
        int v = sh_wsum[lane];
        int inc = v;
        #pragma unroll
        for (int off = 1; off < 32; off <<= 1) {
            int t = __shfl_up_sync(0xFFFFFFFFu, inc, off);
            if (lane >= off) inc += t;
        }
        sh_wpre[lane] = inc - v;
        if (lane == 31) sh_total = inc;   // total fg count
    }
    __syncthreads();

    if (tid < HW) {
        int fgpre = sh_wpre[w] + lanepre;
        int pos = f ? fgpre : (sh_total + (tid - fgpre));
        out[b * HW + pos] = (float)(tid + 1);   // __output__ is float32
    }
}

extern "C" void kernel_launch(void* const* d_in, const int* in_sizes, int n_in,
                              void* d_out, int out_size)
{
    (void)in_sizes; (void)n_in; (void)out_size;
    const float* att = (const float*)d_in[0];
    float* out = (float*)d_out;

    dim3 gridA(12, 32);
    phaseA_kernel<<<gridA, 224>>>(att);
    maskgen_kernel<<<32, 1024>>>(out);
}

// round 8
// speedup vs baseline: 1.2691x; 1.2691x over previous
#include <cuda_runtime.h>
#include <cstdint>

#define MAPSZ 38809      // 197*197
#define NP    196        // 14*14 patches
#define HW    784        // 28*28
#define FULLM 0xFFFFFFFFu

// scratch[z][(i*32 + b)*196 + p] = sum over 6 heads (z half) of att[i,b,j,0,1+p]
__device__ float g_scratch[2][12 * 32 * NP];

// ---------------- Kernel 1: wide phase-A reduction (768 blocks) ----------------
__global__ __launch_bounds__(224)
void phaseA_kernel(const float* __restrict__ att)
{
    const int i = blockIdx.x;      // layer 0..11
    const int b = blockIdx.y;      // batch 0..31
    const int z = blockIdx.z;      // head half 0..1
    const int p = threadIdx.x;     // patch 0..195
    if (p >= NP) return;

    const float* base = att + (size_t)(i * 384 + b * 12 + z * 6) * MAPSZ + 1 + p;
    float s0, s1, s2;
    s0 = __ldg(base + (size_t)0 * MAPSZ) + __ldg(base + (size_t)3 * MAPSZ);
    s1 = __ldg(base + (size_t)1 * MAPSZ) + __ldg(base + (size_t)4 * MAPSZ);
    s2 = __ldg(base + (size_t)2 * MAPSZ) + __ldg(base + (size_t)5 * MAPSZ);
    g_scratch[z][(i * 32 + b) * NP + p] = s0 + (s1 + s2);
}

// Kogge-Stone full-run horizontal fill: all bits of runs of m that intersect f.
__device__ __forceinline__ uint32_t fillH(uint32_t f, uint32_t m)
{
    uint32_t g = f, p = m;
    g |= p & (g << 1); p &= (p << 1);
    g |= p & (g << 2); p &= (p << 2);
    g |= p & (g << 4); p &= (p << 4);
    g |= p & (g << 8);
    uint32_t h = f, q = m;
    h |= q & (h >> 1); q &= (q >> 1);
    h |= q & (h >> 2); q &= (q >> 2);
    h |= q & (h >> 4); q &= (q >> 4);
    h |= q & (h >> 8);
    return (g | h) & m;
}

// ---------------- Kernel 2: threshold, bit-CCL, compaction (32 blocks) ----------------
__global__ __launch_bounds__(1024, 1)
void maskgen_kernel(float* __restrict__ out)
{
    __shared__ float sh_a14[NP];        // 14x14 attention means
    __shared__ float sh_red[256];       // threshold reduction
    __shared__ unsigned sh_final[14];   // final 14x14 mask, one 14-bit row per entry
    __shared__ int   sh_wsum[32], sh_wpre[32];
    __shared__ int   sh_total;
    __shared__ float sh_thr;

    const int b    = blockIdx.x;
    const int tid  = threadIdx.x;
    const int lane = tid & 31;
    const int w    = tid >> 5;

    // ---------- gather partial sums (L2-resident scratch) ----------
    if (tid < NP) {
        float s0 = 0.f, s1 = 0.f, s2 = 0.f, s3 = 0.f;
        #pragma unroll
        for (int i = 0; i < 12; i += 4) {
            s0 += g_scratch[0][((i + 0) * 32 + b) * NP + tid] + g_scratch[1][((i + 0) * 32 + b) * NP + tid];
            s1 += g_scratch[0][((i + 1) * 32 + b) * NP + tid] + g_scratch[1][((i + 1) * 32 + b) * NP + tid];
            s2 += g_scratch[0][((i + 2) * 32 + b) * NP + tid] + g_scratch[1][((i + 2) * 32 + b) * NP + tid];
            s3 += g_scratch[0][((i + 3) * 32 + b) * NP + tid] + g_scratch[1][((i + 3) * 32 + b) * NP + tid];
        }
        sh_a14[tid] = ((s0 + s1) + (s2 + s3)) / 144.0f;
    }
    __syncthreads();

    // ---------- threshold = mean of a14 (== mean of the 28x28 upsample) ----------
    if (tid < 256) sh_red[tid] = (tid < NP) ? sh_a14[tid] : 0.f;
    __syncthreads();
    for (int s = 128; s > 0; s >>= 1) {
        if (tid < s) sh_red[tid] += sh_red[tid + s];
        __syncthreads();
    }
    if (tid == 0) sh_thr = sh_red[0] / 196.0f;
    __syncthreads();
    const float thr = sh_thr;

    // ---------- warp 0: bit-parallel CCL at 14x14 (no block barriers) ----------
    // 28x28 connectivity == 14x14 connectivity (2x nearest upsample); areas scale 4x;
    // seeds taken in ascending flat order => first max wins ties (== argmax semantics).
    if (w == 0) {
        // build row mask: lane y holds 14 bits
        uint32_t m = 0;
        if (lane < 14) {
            #pragma unroll
            for (int x = 0; x < 14; ++x)
                m |= (sh_a14[lane * 14 + x] > thr) ? (1u << x) : 0u;
        }
        uint32_t m_rem = m;
        uint32_t best_f = 0;
        int best_area = 0;

        while (true) {
            unsigned rows = __ballot_sync(FULLM, m_rem != 0);
            if (!rows) break;
            int sr = __ffs(rows) - 1;                       // lowest row with fg
            uint32_t srow = __shfl_sync(FULLM, m_rem, sr);
            uint32_t f = (lane == sr) ? (srow & (0u - srow)) : 0u;  // lowest bit = seed

            // flood: full horizontal runs + 1 vertical step per iteration
            while (true) {
                uint32_t fh = fillH(f, m_rem);
                uint32_t up = __shfl_up_sync(FULLM, fh, 1);
                uint32_t dn = __shfl_down_sync(FULLM, fh, 1);
                if (lane == 0)  up = 0;
                if (lane == 31) dn = 0;
                uint32_t nf = (fh | up | dn) & m_rem;
                unsigned ch = __ballot_sync(FULLM, nf != f);
                f = nf;
                if (!ch) break;
            }

            int area = __reduce_add_sync(FULLM, __popc(f));
            if (area > best_area) { best_area = area; best_f = f; }
            m_rem &= ~f;
        }

        const bool keep = (best_area * 4 >= 160);           // THRESHOLD_POINT at 28x28
        uint32_t fin = keep ? best_f : m;
        if (lane < 14) sh_final[lane] = fin;
        if (lane == 0) sh_total = 0;   // placeholder init (overwritten below)
    }
    __syncthreads();

    // ---------- final 28x28 mask + stable "fg first, then bg" compaction ----------
    int f = 0;
    if (tid < HW) {
        int y = tid / 28, x = tid - y * 28;
        f = (sh_final[y >> 1] >> (x >> 1)) & 1;
    }
    unsigned bal = __ballot_sync(FULLM, f);
    const int lanepre = __popc(bal & ((1u << lane) - 1));
    if (lane == 0) sh_wsum[w] = __popc(bal);
    __syncthreads();
    if (w == 0) {
        int v = sh_wsum[lane];
        int inc = v;
        #pragma unroll
        for (int off = 1; off < 32; off <<= 1) {
            int t = __shfl_up_sync(FULLM, inc, off);
            if (lane >= off) inc += t;
        }
        sh_wpre[lane] = inc - v;
        if (lane == 31) sh_total = inc;   // total fg count
    }
    __syncthreads();

    if (tid < HW) {
        int fgpre = sh_wpre[w] + lanepre;
        int pos = f ? fgpre : (sh_total + (tid - fgpre));
        out[b * HW + pos] = (float)(tid + 1);   // __output__ is float32
    }
}

extern "C" void kernel_launch(void* const* d_in, const int* in_sizes, int n_in,
                              void* d_out, int out_size)
{
    (void)in_sizes; (void)n_in; (void)out_size;
    const float* att = (const float*)d_in[0];
    float* out = (float*)d_out;

    dim3 gridA(12, 32, 2);
    phaseA_kernel<<<gridA, 224>>>(att);
    maskgen_kernel<<<32, 1024>>>(out);
}

// round 9
// speedup vs baseline: 1.4717x; 1.1597x over previous
#include <cuda_runtime.h>
#include <cstdint>

#define MAPSZ 38809      // 197*197
#define NP    196        // 14*14 patches
#define HW    784        // 28*28
#define FULLM 0xFFFFFFFFu

// scratch[z][(i*32 + b)*196 + p] = sum over 6 heads (z half) of att[i,b,j,0,1+p]
__device__ float g_scratch[2][12 * 32 * NP];

// ---------------- Kernel 1: wide phase-A reduction (768 blocks) ----------------
__global__ __launch_bounds__(224)
void phaseA_kernel(const float* __restrict__ att)
{
    const int i = blockIdx.x;      // layer 0..11
    const int b = blockIdx.y;      // batch 0..31
    const int z = blockIdx.z;      // head half 0..1
    const int p = threadIdx.x;     // patch 0..195
    if (p >= NP) return;

    const float* base = att + (size_t)(i * 384 + b * 12 + z * 6) * MAPSZ + 1 + p;
    float s0, s1, s2;
    s0 = __ldg(base + (size_t)0 * MAPSZ) + __ldg(base + (size_t)3 * MAPSZ);
    s1 = __ldg(base + (size_t)1 * MAPSZ) + __ldg(base + (size_t)4 * MAPSZ);
    s2 = __ldg(base + (size_t)2 * MAPSZ) + __ldg(base + (size_t)5 * MAPSZ);
    g_scratch[z][(i * 32 + b) * NP + p] = s0 + (s1 + s2);
}

// Kogge-Stone full-run horizontal fill: all bits of runs of m intersecting f.
__device__ __forceinline__ uint32_t fillH(uint32_t f, uint32_t m)
{
    uint32_t g = f, p = m;
    g |= p & (g << 1); p &= (p << 1);
    g |= p & (g << 2); p &= (p << 2);
    g |= p & (g << 4); p &= (p << 4);
    g |= p & (g << 8);
    uint32_t h = f, q = m;
    h |= q & (h >> 1); q &= (q >> 1);
    h |= q & (h >> 2); q &= (q >> 2);
    h |= q & (h >> 4); q &= (q >> 4);
    h |= q & (h >> 8);
    return (g | h) & m;
}

// ---------------- Kernel 2: threshold, parallel bit-CCL, compaction ----------------
__global__ __launch_bounds__(1024, 1)
void maskgen_kernel(float* __restrict__ out)
{
    __shared__ float    sh_a14[NP];     // 14x14 attention means
    __shared__ float    sh_part[8];     // warp partial sums for threshold
    __shared__ unsigned sh_m[14];       // 14x14 mask rows
    __shared__ unsigned sh_rs[14];      // run-start bits per row
    __shared__ unsigned sh_final[14];   // final mask rows
    __shared__ int      sh_nruns, sh_key, sh_total;
    __shared__ float    sh_thr;
    __shared__ int      sh_wsum[32], sh_wpre[32];

    const int b    = blockIdx.x;
    const int tid  = threadIdx.x;
    const int lane = tid & 31;
    const int w    = tid >> 5;

    // ---------- gather partial sums (L2-resident scratch) + per-warp reduce ----------
    float a = 0.f;
    if (tid < NP) {
        float s0 = 0.f, s1 = 0.f, s2 = 0.f, s3 = 0.f;
        #pragma unroll
        for (int i = 0; i < 12; i += 4) {
            s0 += g_scratch[0][((i + 0) * 32 + b) * NP + tid] + g_scratch[1][((i + 0) * 32 + b) * NP + tid];
            s1 += g_scratch[0][((i + 1) * 32 + b) * NP + tid] + g_scratch[1][((i + 1) * 32 + b) * NP + tid];
            s2 += g_scratch[0][((i + 2) * 32 + b) * NP + tid] + g_scratch[1][((i + 2) * 32 + b) * NP + tid];
            s3 += g_scratch[0][((i + 3) * 32 + b) * NP + tid] + g_scratch[1][((i + 3) * 32 + b) * NP + tid];
        }
        a = ((s0 + s1) + (s2 + s3)) / 144.0f;
        sh_a14[tid] = a;
    }
    if (w < 7) {                                 // tids 0..223 cover all 196 values
        float v = a;
        #pragma unroll
        for (int off = 16; off > 0; off >>= 1)
            v += __shfl_down_sync(FULLM, v, off);
        if (lane == 0) sh_part[w] = v;
    }
    if (tid == 0) { sh_key = 0; }
    __syncthreads();

    // ---------- warp 0: threshold, mask rows, run-starts ----------
    if (w == 0) {
        float v = (lane < 7) ? sh_part[lane] : 0.f;
        #pragma unroll
        for (int off = 16; off > 0; off >>= 1)
            v += __shfl_down_sync(FULLM, v, off);
        float thr = __shfl_sync(FULLM, v, 0) / 196.0f;
        if (lane == 0) sh_thr = thr;

        uint32_t m = 0;
        if (lane < 14) {
            #pragma unroll
            for (int x = 0; x < 14; ++x)
                m |= (sh_a14[lane * 14 + x] > thr) ? (1u << x) : 0u;
            sh_m[lane] = m;
            sh_rs[lane] = m & ~(m << 1);
        }
        int nr = __reduce_add_sync(FULLM, (lane < 14) ? __popc(m & ~(m << 1)) : 0);
        if (lane == 0) sh_nruns = nr;
    }
    __syncthreads();

    // ---------- all warps: parallel flood-fill CCL at 14x14 ----------
    // 28x28 connectivity == 14x14 (2x nearest upsample); areas scale exactly 4x.
    // Every component's min cell is a run-start; warp w handles seeds w, w+32, ...
    const uint32_t mrow  = (lane < 14) ? sh_m[lane]  : 0u;
    const uint32_t rsrow = (lane < 14) ? sh_rs[lane] : 0u;
    const int nruns = sh_nruns;

    // exclusive prefix of run-start counts per row (lane = row)
    int cnt = __popc(rsrow);
    int pre = cnt;
    #pragma unroll
    for (int off = 1; off < 32; off <<= 1) {
        int t = __shfl_up_sync(FULLM, pre, off);
        if (lane >= off) pre += t;
    }
    const int excl = pre - cnt;

    int      key_best = 0;
    uint32_t fbest    = 0;

    for (int k = w; k < nruns; k += 32) {
        unsigned sel = __ballot_sync(FULLM, (k >= excl) && (k < excl + cnt));
        int row = __ffs(sel) - 1;
        int j   = k - __shfl_sync(FULLM, excl, row);
        uint32_t bits = __shfl_sync(FULLM, rsrow, row);
        for (int t = 0; t < j; ++t) bits &= bits - 1;
        uint32_t f = (lane == row) ? (bits & (0u - bits)) : 0u;

        // flood: full horizontal runs + 1 vertical step per iteration
        while (true) {
            uint32_t fh = fillH(f, mrow);
            uint32_t up = __shfl_up_sync(FULLM, fh, 1);
            uint32_t dn = __shfl_down_sync(FULLM, fh, 1);
            if (lane == 0)  up = 0;
            if (lane == 31) dn = 0;
            uint32_t nf = fh | ((up | dn) & mrow);
            unsigned ch = __ballot_sync(FULLM, nf != f);
            f = nf;
            if (!ch) break;
        }

        int area = __reduce_add_sync(FULLM, __popc(f));
        unsigned nz = __ballot_sync(FULLM, f != 0);
        int r0 = __ffs(nz) - 1;
        uint32_t fr0 = __shfl_sync(FULLM, f, r0);
        int mincell = r0 * 14 + (__ffs(fr0) - 1);
        int key = (area << 8) | (255 - mincell);   // max area, tie -> min label
        if (key > key_best) { key_best = key; fbest = f; }
    }
    if (lane == 0 && key_best > 0) atomicMax(&sh_key, key_best);
    __syncthreads();

    const int gkey = sh_key;
    if (key_best == gkey) {                        // winner(s) write identical data
        const bool keep = ((gkey >> 8) * 4 >= 160);  // THRESHOLD_POINT at 28x28
        if (lane < 14) sh_final[lane] = keep ? fbest : mrow;
    }
    __syncthreads();

    // ---------- final 28x28 mask + stable "fg first, then bg" compaction ----------
    int f = 0;
    if (tid < HW) {
        int y = tid / 28, x = tid - y * 28;
        f = (sh_final[y >> 1] >> (x >> 1)) & 1;
    }
    unsigned bal = __ballot_sync(FULLM, f);
    const int lanepre = __popc(bal & ((1u << lane) - 1));
    if (lane == 0) sh_wsum[w] = __popc(bal);
    __syncthreads();
    if (w == 0) {
        int v = sh_wsum[lane];
        int inc = v;
        #pragma unroll
        for (int off = 1; off < 32; off <<= 1) {
            int t = __shfl_up_sync(FULLM, inc, off);
            if (lane >= off) inc += t;
        }
        sh_wpre[lane] = inc - v;
        if (lane == 31) sh_total = inc;   // total fg count
    }
    __syncthreads();

    if (tid < HW) {
        int fgpre = sh_wpre[w] + lanepre;
        int pos = f ? fgpre : (sh_total + (tid - fgpre));
        out[b * HW + pos] = (float)(tid + 1);   // __output__ is float32
    }
}

extern "C" void kernel_launch(void* const* d_in, const int* in_sizes, int n_in,
                              void* d_out, int out_size)
{
    (void)in_sizes; (void)n_in; (void)out_size;
    const float* att = (const float*)d_in[0];
    float* out = (float*)d_out;

    dim3 gridA(12, 32, 2);
    phaseA_kernel<<<gridA, 224>>>(att);
    maskgen_kernel<<<32, 1024>>>(out);
}